// round 15
// baseline (speedup 1.0000x reference)
#include <cuda_runtime.h>
#include <math.h>

// Problem shape: B=16, S=2048, D=768
#define MAXB 16
#define MAXS 2048
#define MAXD 768
#define NCHUNK 16   // o-dim chunks for fuse partials

// Scratch (device globals — no allocation allowed)
__device__ float g_part[NCHUNK * MAXD * 3];  // fuse partials [chunk][p]
__device__ float g_w2[MAXD * 3];             // fused conv*linear weights [i*3+k]
__device__ float g_c;                        // fused bias
__device__ float g_z0[MAXB * MAXS];          // per-row dot with w2[:,k]
__device__ float g_z1[MAXB * MAXS];
__device__ float g_z2[MAXB * MAXS];
__device__ float g_alpha[MAXB * MAXS];
__device__ int   g_Ft[MAXB * MAXS];          // fire time indices (compacted)
__device__ float g_Fa1[MAXB * MAXS];         // a1 at fire j
__device__ float g_Fa2[MAXB * MAXS];         // a2 at fire j
__device__ int   g_n[MAXB];

// ---------------------------------------------------------------------------
// Kernel 1a: partial fuse. grid = (9 p-blocks, NCHUNK o-chunks), 256 thr.
// ---------------------------------------------------------------------------
__global__ void k_fuse_part(const float* __restrict__ conv_w,
                            const float* __restrict__ lin_w, int D) {
    const int p = blockIdx.x * 256 + threadIdx.x;     // p = i*3+k
    const int P = D * 3;
    if (p >= P) return;
    const int ch = blockIdx.y;
    const int csz = D / NCHUNK;
    const int o0 = ch * csz;
    float acc = 0.f;
    #pragma unroll 4
    for (int o = o0; o < o0 + csz; o++)
        acc += lin_w[o] * conv_w[(size_t)o * P + p];
    g_part[ch * P + p] = acc;
}

// ---------------------------------------------------------------------------
// Kernel 1b: combine partials (fixed order) + c scalar.
// ---------------------------------------------------------------------------
__global__ void k_fuse_comb(const float* __restrict__ conv_b,
                            const float* __restrict__ lin_w,
                            const float* __restrict__ lin_b, int D) {
    const int P = D * 3;
    if ((int)blockIdx.x == (int)gridDim.x - 1) {
        __shared__ float red[256];
        float s = 0.f;
        for (int o = threadIdx.x; o < D; o += 256) s += lin_w[o] * conv_b[o];
        red[threadIdx.x] = s;
        __syncthreads();
        for (int st = 128; st > 0; st >>= 1) {
            if ((int)threadIdx.x < st) red[threadIdx.x] += red[threadIdx.x + st];
            __syncthreads();
        }
        if (threadIdx.x == 0) g_c = red[0] + lin_b[0];
    } else {
        int p = blockIdx.x * 256 + threadIdx.x;
        if (p < P) {
            float acc = 0.f;
            #pragma unroll
            for (int ch = 0; ch < NCHUNK; ch++) acc += g_part[ch * P + p];
            g_w2[p] = acc;
        }
    }
}

// ---------------------------------------------------------------------------
// Kernel 2: z_k[r] = dot(x[r], w2[:,k]). Warp per row, 8 warps/blk. (R12)
// ---------------------------------------------------------------------------
__global__ void k_z(const float* __restrict__ x, int S, int D) {
    __shared__ __align__(16) float sw2[3 * MAXD];
    for (int idx = threadIdx.x; idx < D * 3; idx += blockDim.x) {
        int i = idx / 3, k = idx - i * 3;
        sw2[k * D + i] = g_w2[idx];
    }
    __syncthreads();

    const int b = blockIdx.y;
    const int warp = threadIdx.x >> 5, lane = threadIdx.x & 31;
    const int r = blockIdx.x * 8 + warp;
    if (r >= S) return;

    const float4* xr  = (const float4*)(x + ((size_t)b * S + r) * D);
    const float4* w0  = (const float4*)(sw2);
    const float4* w1  = (const float4*)(sw2 + D);
    const float4* w2p = (const float4*)(sw2 + 2 * D);
    float a0 = 0.f, a1 = 0.f, a2 = 0.f;

    if (D == MAXD) {
        float4 xv[6];
        #pragma unroll
        for (int u = 0; u < 6; u++) xv[u] = xr[lane + 32 * u];
        #pragma unroll
        for (int u = 0; u < 6; u++) {
            const int m = lane + 32 * u;
            float4 uu = w0[m];
            a0 += uu.x * xv[u].x + uu.y * xv[u].y + uu.z * xv[u].z + uu.w * xv[u].w;
            float4 vv = w1[m];
            a1 += vv.x * xv[u].x + vv.y * xv[u].y + vv.z * xv[u].z + vv.w * xv[u].w;
            float4 ww = w2p[m];
            a2 += ww.x * xv[u].x + ww.y * xv[u].y + ww.z * xv[u].z + ww.w * xv[u].w;
        }
    } else {
        const int M = D >> 2;
        for (int m = lane; m < M; m += 32) {
            float4 xv = xr[m];
            float4 uu = w0[m];
            a0 += uu.x * xv.x + uu.y * xv.y + uu.z * xv.z + uu.w * xv.w;
            float4 vv = w1[m];
            a1 += vv.x * xv.x + vv.y * xv.y + vv.z * xv.z + vv.w * xv.w;
            float4 ww = w2p[m];
            a2 += ww.x * xv.x + ww.y * xv.y + ww.z * xv.z + ww.w * xv.w;
        }
    }
    #pragma unroll
    for (int o = 16; o > 0; o >>= 1) {
        a0 += __shfl_xor_sync(0xffffffffu, a0, o);
        a1 += __shfl_xor_sync(0xffffffffu, a1, o);
        a2 += __shfl_xor_sync(0xffffffffu, a2, o);
    }
    if (lane == 0) {
        size_t idx = (size_t)b * S + r;
        g_z0[idx] = a0; g_z1[idx] = a1; g_z2[idx] = a2;
    }
}

// ---------------------------------------------------------------------------
// Kernel 3: alpha — wide grid (proven 5 µs).
// ---------------------------------------------------------------------------
__global__ void k_comb(const int* __restrict__ lens, int B, int S) {
    int idx = blockIdx.x * 256 + threadIdx.x;
    if (idx >= B * S) return;
    int b = idx / S, t = idx - b * S;
    float a = 0.f;
    if (t < lens[b]) {
        float l = g_c + g_z1[idx];
        if (t > 0)     l += g_z0[idx - 1];
        if (t < S - 1) l += g_z2[idx + 1];
        a = 1.f / (1.f + expf(-l));
    }
    g_alpha[idx] = a;
}

// ---------------------------------------------------------------------------
// Short-recurrence chain step (validated R10-R14).
// ---------------------------------------------------------------------------
#define CHAINSTEP(aval)                                \
    {   float a   = (aval);                            \
        float s1  = aacc + a;                          \
        float sm1 = s1 - 1.0f;                         \
        bool fire = (s1 >= 1.0f);                      \
        BODY                                           \
        aacc = fire ? sm1 : s1;                        \
        bit++;                                         \
    }
#define CHAIN8(q)  CHAINSTEP((q).x) CHAINSTEP((q).y) CHAINSTEP((q).z) CHAINSTEP((q).w)
#define CHAIN32    { CHAIN8(v0) } { CHAIN8(v1) } { CHAIN8(v2) } { CHAIN8(v3) } \
                   { CHAIN8(v4) } { CHAIN8(v5) } { CHAIN8(v6) } { CHAIN8(v7) }

// ---------------------------------------------------------------------------
// Kernel 4: CIF scan, zero serial phase (validated R14). Monotone positive
// alphas => carry before chunk cb = fract(exclusive prefix of chunk sums);
// Hillis-Steele shfl double prefix over 64 chunks, then float mask/record
// replay from checkpoints.
// ---------------------------------------------------------------------------
__global__ void k_scan(int S) {
    __shared__ __align__(16) float sa[MAXS];
    __shared__ double sWT;                    // warp-0 total (carry)
    __shared__ float  sChk[MAXS / 32];
    __shared__ unsigned int sMask[MAXS / 32];
    __shared__ int    sNfb[MAXS / 32];
    const int b = blockIdx.x;
    const int base = b * S;
    const int NC = S >> 5;   // 64 chunks of 32

    {
        const float4* src = (const float4*)(g_alpha + base);
        float4* dst = (float4*)sa;
        for (int m = threadIdx.x; m < (S >> 2); m += blockDim.x)
            dst[m] = src[m];
    }
    __syncthreads();

    double v = 0.0, inc = 0.0;
    if ((int)threadIdx.x < NC) {
        const float* p = sa + (threadIdx.x << 5);
        #pragma unroll
        for (int u = 0; u < 32; u++) v += (double)p[u];
        inc = v;
        const int lane = threadIdx.x & 31;
        #pragma unroll
        for (int off = 1; off < 32; off <<= 1) {
            double nv = __shfl_up_sync(0xffffffffu, inc, off);
            if (lane >= off) inc += nv;
        }
    }
    __syncthreads();
    if (threadIdx.x == 31) sWT = inc;
    __syncthreads();
    if ((int)threadIdx.x < NC) {
        if ((int)threadIdx.x >= 32) inc += sWT;
        double pexc = inc - v;                // exclusive prefix
        sChk[threadIdx.x] = (float)(pexc - floor(pexc));
    }
    __syncthreads();

    if ((int)threadIdx.x < NC) {
        const int cb = threadIdx.x;
        float aacc = sChk[cb];
        const float4* q = (const float4*)(sa + (cb << 5));
        float4 v0 = q[0], v1 = q[1], v2 = q[2], v3 = q[3];
        float4 v4 = q[4], v5 = q[5], v6 = q[6], v7 = q[7];
        unsigned int mask = 0u;
        int bit = 0;
        #define BODY mask |= fire ? (1u << bit) : 0u;
        CHAIN32
        #undef BODY
        sMask[cb] = mask;
    }
    __syncthreads();

    if ((int)threadIdx.x < NC) {
        int cnt = 0;
        for (int j = 0; j < (int)threadIdx.x; j++) cnt += __popc(sMask[j]);
        sNfb[threadIdx.x] = cnt;
        if ((int)threadIdx.x == NC - 1)
            g_n[b] = cnt + __popc(sMask[NC - 1]);
    }
    __syncthreads();

    if ((int)threadIdx.x < NC) {
        const int cb = threadIdx.x;
        if (sMask[cb]) {
            float aacc = sChk[cb];
            int pos = base + sNfb[cb];
            const int t0c = cb << 5;
            const float4* q = (const float4*)(sa + t0c);
            float4 v0 = q[0], v1 = q[1], v2 = q[2], v3 = q[3];
            float4 v4 = q[4], v5 = q[5], v6 = q[6], v7 = q[7];
            int bit = 0;
            #define BODY if (fire) { float ra1 = 1.0f - aacc;      \
                                     float ra2 = a - ra1;          \
                                     g_Ft[pos] = t0c + bit;        \
                                     g_Fa1[pos] = ra1;             \
                                     g_Fa2[pos] = ra2; pos++; }
            CHAIN32
            #undef BODY
        }
    }
}

// ---------------------------------------------------------------------------
// Kernel 5: emit — ONLY change this round: 768-thread block = 4 independent
// 192-thread row-groups running their segment t-loops CONCURRENTLY (4x the
// in-flight loads; block time = max over 4 segments instead of sum).
// Math identical: row j < n: weighted sum over t in [F[j-1], F[j]];
// rows >= n: zeros.
// ---------------------------------------------------------------------------
__global__ void k_emit(const float* __restrict__ x, float* __restrict__ out,
                       int B, int S, int D, long long out_size) {
    const int tpr = D >> 2;                 // 192 threads per row
    const int sg  = threadIdx.x / tpr;      // row-group 0..3
    const int tid = threadIdx.x - sg * tpr;
    const int b = blockIdx.y;
    const int j = blockIdx.x * 4 + sg;
    const int n = g_n[b];
    const int base = b * S;

    if (j < S) {
        float4* orow = (float4*)(out + ((size_t)b * S + j) * D);
        if (j >= n) {
            orow[tid] = make_float4(0.f, 0.f, 0.f, 0.f);
        } else {
            const int t1 = g_Ft[base + j];
            const int t0 = (j == 0) ? 0 : g_Ft[base + j - 1];
            const float wa1 = g_Fa1[base + j];
            const float wa2 = (j == 0) ? 0.f : g_Fa2[base + j - 1];
            float4 acc = make_float4(0.f, 0.f, 0.f, 0.f);
            #pragma unroll 4
            for (int t = t0; t <= t1; t++) {
                float wgt = (t == t1) ? wa1
                          : ((j > 0 && t == t0) ? wa2 : g_alpha[base + t]);
                const float4 h = ((const float4*)(x + ((size_t)b * S + t) * D))[tid];
                acc.x += wgt * h.x; acc.y += wgt * h.y;
                acc.z += wgt * h.z; acc.w += wgt * h.w;
            }
            orow[tid] = acc;
        }
    }
    if (blockIdx.x == 0 && threadIdx.x == 0 &&
        out_size >= (long long)B * S * D + B)
        out[(size_t)B * S * D + b] = (float)n;
}

// ---------------------------------------------------------------------------
extern "C" void kernel_launch(void* const* d_in, const int* in_sizes, int n_in,
                              void* d_out, int out_size) {
    const float* x      = (const float*)d_in[0];  // (B,S,D)
    const int*   lens   = (const int*)  d_in[1];  // (B,)
    const float* conv_w = (const float*)d_in[2];  // (D,D,3)
    const float* conv_b = (const float*)d_in[3];  // (D,)
    const float* lin_w  = (const float*)d_in[4];  // (1,D)
    const float* lin_b  = (const float*)d_in[5];  // (1,)

    const int B = in_sizes[1];
    const int D = in_sizes[4];
    const int S = in_sizes[0] / (B * D);
    float* out = (float*)d_out;

    {
        dim3 g1((D * 3 + 255) / 256, NCHUNK);
        k_fuse_part<<<g1, 256>>>(conv_w, lin_w, D);
        k_fuse_comb<<<(D * 3 + 255) / 256 + 1, 256>>>(conv_b, lin_w, lin_b, D);
    }
    {
        dim3 grid((S + 7) / 8, B);
        k_z<<<grid, 256>>>(x, S, D);
    }
    k_comb<<<(B * S + 255) / 256, 256>>>(lens, B, S);   // wide alpha pass
    k_scan<<<B, 256>>>(S);                               // parallel-prefix scan
    {
        dim3 grid((S + 3) / 4, B);
        k_emit<<<grid, D>>>(x, out, B, S, D, (long long)out_size);  // 768 thr
    }
}

// round 16
// speedup vs baseline: 1.4387x; 1.4387x over previous
#include <cuda_runtime.h>
#include <math.h>

// Problem shape: B=16, S=2048, D=768
#define MAXB 16
#define MAXS 2048
#define MAXD 768
#define NCHUNK 16   // o-dim chunks for fuse partials

// Scratch (device globals — no allocation allowed)
__device__ float g_part[NCHUNK * MAXD * 3];  // fuse partials [chunk][p]
__device__ float g_w2[MAXD * 3];             // fused conv*linear weights [i*3+k]
__device__ float g_c;                        // fused bias
__device__ float g_z0[MAXB * MAXS];          // per-row dot with w2[:,k]
__device__ float g_z1[MAXB * MAXS];
__device__ float g_z2[MAXB * MAXS];
__device__ float g_alpha[MAXB * MAXS];
__device__ double g_csum[MAXB * (MAXS / 32)];// per-chunk double alpha sums
__device__ int   g_Ft[MAXB * MAXS];          // fire time indices (compacted)
__device__ float g_Fa1[MAXB * MAXS];         // a1 at fire j
__device__ float g_Fa2[MAXB * MAXS];         // a2 at fire j
__device__ int   g_n[MAXB];

// ---------------------------------------------------------------------------
// Kernel 1a: partial fuse. grid = (9 p-blocks, NCHUNK o-chunks), 256 thr.
// ---------------------------------------------------------------------------
__global__ void k_fuse_part(const float* __restrict__ conv_w,
                            const float* __restrict__ lin_w, int D) {
    const int p = blockIdx.x * 256 + threadIdx.x;     // p = i*3+k
    const int P = D * 3;
    if (p >= P) return;
    const int ch = blockIdx.y;
    const int csz = D / NCHUNK;
    const int o0 = ch * csz;
    float acc = 0.f;
    #pragma unroll 4
    for (int o = o0; o < o0 + csz; o++)
        acc += lin_w[o] * conv_w[(size_t)o * P + p];
    g_part[ch * P + p] = acc;
}

// ---------------------------------------------------------------------------
// Kernel 1b: combine partials (fixed order) + c scalar.
// ---------------------------------------------------------------------------
__global__ void k_fuse_comb(const float* __restrict__ conv_b,
                            const float* __restrict__ lin_w,
                            const float* __restrict__ lin_b, int D) {
    const int P = D * 3;
    if ((int)blockIdx.x == (int)gridDim.x - 1) {
        __shared__ float red[256];
        float s = 0.f;
        for (int o = threadIdx.x; o < D; o += 256) s += lin_w[o] * conv_b[o];
        red[threadIdx.x] = s;
        __syncthreads();
        for (int st = 128; st > 0; st >>= 1) {
            if ((int)threadIdx.x < st) red[threadIdx.x] += red[threadIdx.x + st];
            __syncthreads();
        }
        if (threadIdx.x == 0) g_c = red[0] + lin_b[0];
    } else {
        int p = blockIdx.x * 256 + threadIdx.x;
        if (p < P) {
            float acc = 0.f;
            #pragma unroll
            for (int ch = 0; ch < NCHUNK; ch++) acc += g_part[ch * P + p];
            g_w2[p] = acc;
        }
    }
}

// ---------------------------------------------------------------------------
// Kernel 2: z_k[r] = dot(x[r], w2[:,k]). Warp per row, 8 warps/blk. (R12)
// ---------------------------------------------------------------------------
__global__ void k_z(const float* __restrict__ x, int S, int D) {
    __shared__ __align__(16) float sw2[3 * MAXD];
    for (int idx = threadIdx.x; idx < D * 3; idx += blockDim.x) {
        int i = idx / 3, k = idx - i * 3;
        sw2[k * D + i] = g_w2[idx];
    }
    __syncthreads();

    const int b = blockIdx.y;
    const int warp = threadIdx.x >> 5, lane = threadIdx.x & 31;
    const int r = blockIdx.x * 8 + warp;
    if (r >= S) return;

    const float4* xr  = (const float4*)(x + ((size_t)b * S + r) * D);
    const float4* w0  = (const float4*)(sw2);
    const float4* w1  = (const float4*)(sw2 + D);
    const float4* w2p = (const float4*)(sw2 + 2 * D);
    float a0 = 0.f, a1 = 0.f, a2 = 0.f;

    if (D == MAXD) {
        float4 xv[6];
        #pragma unroll
        for (int u = 0; u < 6; u++) xv[u] = xr[lane + 32 * u];
        #pragma unroll
        for (int u = 0; u < 6; u++) {
            const int m = lane + 32 * u;
            float4 uu = w0[m];
            a0 += uu.x * xv[u].x + uu.y * xv[u].y + uu.z * xv[u].z + uu.w * xv[u].w;
            float4 vv = w1[m];
            a1 += vv.x * xv[u].x + vv.y * xv[u].y + vv.z * xv[u].z + vv.w * xv[u].w;
            float4 ww = w2p[m];
            a2 += ww.x * xv[u].x + ww.y * xv[u].y + ww.z * xv[u].z + ww.w * xv[u].w;
        }
    } else {
        const int M = D >> 2;
        for (int m = lane; m < M; m += 32) {
            float4 xv = xr[m];
            float4 uu = w0[m];
            a0 += uu.x * xv.x + uu.y * xv.y + uu.z * xv.z + uu.w * xv.w;
            float4 vv = w1[m];
            a1 += vv.x * xv.x + vv.y * xv.y + vv.z * xv.z + vv.w * xv.w;
            float4 ww = w2p[m];
            a2 += ww.x * xv.x + ww.y * xv.y + ww.z * xv.z + ww.w * xv.w;
        }
    }
    #pragma unroll
    for (int o = 16; o > 0; o >>= 1) {
        a0 += __shfl_xor_sync(0xffffffffu, a0, o);
        a1 += __shfl_xor_sync(0xffffffffu, a1, o);
        a2 += __shfl_xor_sync(0xffffffffu, a2, o);
    }
    if (lane == 0) {
        size_t idx = (size_t)b * S + r;
        g_z0[idx] = a0; g_z1[idx] = a1; g_z2[idx] = a2;
    }
}

// ---------------------------------------------------------------------------
// Kernel 3: alpha (wide grid) + NEW: per-chunk double sums. S is a multiple
// of 256, so each block covers 8 aligned 32-chunks of one batch; each warp
// butterfly-reduces its 32 alphas in double (fixed association) and lane 0
// writes g_csum. This moves the chunk-sum phase out of the 16-block scan
// kernel into a 128-block one.
// ---------------------------------------------------------------------------
__global__ void k_comb(const int* __restrict__ lens, int B, int S) {
    int idx = blockIdx.x * 256 + threadIdx.x;
    float a = 0.f;
    if (idx < B * S) {
        int b = idx / S, t = idx - b * S;
        if (t < lens[b]) {
            float l = g_c + g_z1[idx];
            if (t > 0)     l += g_z0[idx - 1];
            if (t < S - 1) l += g_z2[idx + 1];
            a = 1.f / (1.f + expf(-l));
        }
        g_alpha[idx] = a;
    }
    // chunk sum (warp == one aligned 32-chunk)
    double d = (double)a;
    #pragma unroll
    for (int o = 16; o > 0; o >>= 1)
        d += __shfl_xor_sync(0xffffffffu, d, o);
    if ((threadIdx.x & 31) == 0 && idx < B * S)
        g_csum[idx >> 5] = d;
}

// ---------------------------------------------------------------------------
// Short-recurrence chain step (validated R10-R14).
// ---------------------------------------------------------------------------
#define CHAINSTEP(aval)                                \
    {   float a   = (aval);                            \
        float s1  = aacc + a;                          \
        float sm1 = s1 - 1.0f;                         \
        bool fire = (s1 >= 1.0f);                      \
        BODY                                           \
        aacc = fire ? sm1 : s1;                        \
        bit++;                                         \
    }
#define CHAIN8(q)  CHAINSTEP((q).x) CHAINSTEP((q).y) CHAINSTEP((q).z) CHAINSTEP((q).w)
#define CHAIN32    { CHAIN8(v0) } { CHAIN8(v1) } { CHAIN8(v2) } { CHAIN8(v3) } \
                   { CHAIN8(v4) } { CHAIN8(v5) } { CHAIN8(v6) } { CHAIN8(v7) }

// ---------------------------------------------------------------------------
// Kernel 4: CIF scan, zero serial phase (validated R14). Chunk sums now
// arrive precomputed from k_comb; this kernel only does the 64-wide shfl
// double prefix + float mask/record replay.
// ---------------------------------------------------------------------------
__global__ void k_scan(int S) {
    __shared__ __align__(16) float sa[MAXS];
    __shared__ double sWT;                    // warp-0 total (carry)
    __shared__ float  sChk[MAXS / 32];
    __shared__ unsigned int sMask[MAXS / 32];
    __shared__ int    sNfb[MAXS / 32];
    const int b = blockIdx.x;
    const int base = b * S;
    const int NC = S >> 5;   // 64 chunks of 32

    // Load alphas for the replay phases (overlaps with prefix math below)
    {
        const float4* src = (const float4*)(g_alpha + base);
        float4* dst = (float4*)sa;
        for (int m = threadIdx.x; m < (S >> 2); m += blockDim.x)
            dst[m] = src[m];
    }

    // Exclusive double prefix over precomputed chunk sums
    double v = 0.0, inc = 0.0;
    if ((int)threadIdx.x < NC) {
        v = g_csum[(base >> 5) + threadIdx.x];
        inc = v;
        const int lane = threadIdx.x & 31;
        #pragma unroll
        for (int off = 1; off < 32; off <<= 1) {
            double nv = __shfl_up_sync(0xffffffffu, inc, off);
            if (lane >= off) inc += nv;
        }
    }
    __syncthreads();
    if (threadIdx.x == 31) sWT = inc;
    __syncthreads();
    if ((int)threadIdx.x < NC) {
        if ((int)threadIdx.x >= 32) inc += sWT;
        double pexc = inc - v;                // exclusive prefix
        sChk[threadIdx.x] = (float)(pexc - floor(pexc));
    }
    __syncthreads();

    // Float replay -> fire masks
    if ((int)threadIdx.x < NC) {
        const int cb = threadIdx.x;
        float aacc = sChk[cb];
        const float4* q = (const float4*)(sa + (cb << 5));
        float4 v0 = q[0], v1 = q[1], v2 = q[2], v3 = q[3];
        float4 v4 = q[4], v5 = q[5], v6 = q[6], v7 = q[7];
        unsigned int mask = 0u;
        int bit = 0;
        #define BODY mask |= fire ? (1u << bit) : 0u;
        CHAIN32
        #undef BODY
        sMask[cb] = mask;
    }
    __syncthreads();

    // Prefix fire counts
    if ((int)threadIdx.x < NC) {
        int cnt = 0;
        for (int j = 0; j < (int)threadIdx.x; j++) cnt += __popc(sMask[j]);
        sNfb[threadIdx.x] = cnt;
        if ((int)threadIdx.x == NC - 1)
            g_n[b] = cnt + __popc(sMask[NC - 1]);
    }
    __syncthreads();

    // Replay again, write compacted records (exact reference formulas)
    if ((int)threadIdx.x < NC) {
        const int cb = threadIdx.x;
        if (sMask[cb]) {
            float aacc = sChk[cb];
            int pos = base + sNfb[cb];
            const int t0c = cb << 5;
            const float4* q = (const float4*)(sa + t0c);
            float4 v0 = q[0], v1 = q[1], v2 = q[2], v3 = q[3];
            float4 v4 = q[4], v5 = q[5], v6 = q[6], v7 = q[7];
            int bit = 0;
            #define BODY if (fire) { float ra1 = 1.0f - aacc;      \
                                     float ra2 = a - ra1;          \
                                     g_Ft[pos] = t0c + bit;        \
                                     g_Fa1[pos] = ra1;             \
                                     g_Fa2[pos] = ra2; pos++; }
            CHAIN32
            #undef BODY
        }
    }
}

// ---------------------------------------------------------------------------
// Kernel 5: emit — EXACT R14/R12 proven version. Block (jb, b): 4 rows
// serial, 192 threads. Row j < n: weighted sum over t in [F[j-1], F[j]];
// rows >= n: zeros.
// ---------------------------------------------------------------------------
__global__ void k_emit(const float* __restrict__ x, float* __restrict__ out,
                       int B, int S, int D, long long out_size) {
    const int b = blockIdx.y;
    const int tid = threadIdx.x;
    const int n = g_n[b];
    const int base = b * S;
    const int j0 = blockIdx.x * 4;

    #pragma unroll
    for (int jj = 0; jj < 4; jj++) {
        const int j = j0 + jj;
        if (j >= S) break;
        float4* orow = (float4*)(out + ((size_t)b * S + j) * D);
        if (j >= n) {
            orow[tid] = make_float4(0.f, 0.f, 0.f, 0.f);
        } else {
            const int t1 = g_Ft[base + j];
            const int t0 = (j == 0) ? 0 : g_Ft[base + j - 1];
            const float wa1 = g_Fa1[base + j];
            const float wa2 = (j == 0) ? 0.f : g_Fa2[base + j - 1];
            float4 acc = make_float4(0.f, 0.f, 0.f, 0.f);
            #pragma unroll 4
            for (int t = t0; t <= t1; t++) {
                float wgt = (t == t1) ? wa1
                          : ((j > 0 && t == t0) ? wa2 : g_alpha[base + t]);
                const float4 h = ((const float4*)(x + ((size_t)b * S + t) * D))[tid];
                acc.x += wgt * h.x; acc.y += wgt * h.y;
                acc.z += wgt * h.z; acc.w += wgt * h.w;
            }
            orow[tid] = acc;
        }
    }
    if (blockIdx.x == 0 && tid == 0 && out_size >= (long long)B * S * D + B)
        out[(size_t)B * S * D + b] = (float)n;
}

// ---------------------------------------------------------------------------
extern "C" void kernel_launch(void* const* d_in, const int* in_sizes, int n_in,
                              void* d_out, int out_size) {
    const float* x      = (const float*)d_in[0];  // (B,S,D)
    const int*   lens   = (const int*)  d_in[1];  // (B,)
    const float* conv_w = (const float*)d_in[2];  // (D,D,3)
    const float* conv_b = (const float*)d_in[3];  // (D,)
    const float* lin_w  = (const float*)d_in[4];  // (1,D)
    const float* lin_b  = (const float*)d_in[5];  // (1,)

    const int B = in_sizes[1];
    const int D = in_sizes[4];
    const int S = in_sizes[0] / (B * D);
    float* out = (float*)d_out;

    {
        dim3 g1((D * 3 + 255) / 256, NCHUNK);
        k_fuse_part<<<g1, 256>>>(conv_w, lin_w, D);
        k_fuse_comb<<<(D * 3 + 255) / 256 + 1, 256>>>(conv_b, lin_w, lin_b, D);
    }
    {
        dim3 grid((S + 7) / 8, B);
        k_z<<<grid, 256>>>(x, S, D);
    }
    k_comb<<<(B * S + 255) / 256, 256>>>(lens, B, S);   // alpha + chunk sums
    k_scan<<<B, 256>>>(S);                               // prefix + replay only
    {
        dim3 grid((S + 3) / 4, B);
        k_emit<<<grid, D / 4>>>(x, out, B, S, D, (long long)out_size);
    }
}

// round 17
// speedup vs baseline: 1.4393x; 1.0004x over previous
#include <cuda_runtime.h>
#include <math.h>

// Problem shape: B=16, S=2048, D=768
#define MAXB 16
#define MAXS 2048
#define MAXD 768
#define NCHUNK 16   // o-dim chunks for fuse partials

// Scratch (device globals — no allocation allowed)
__device__ float g_part[NCHUNK * MAXD * 3];  // fuse partials [chunk][p]
__device__ float g_w2[MAXD * 3];             // fused conv*linear weights [i*3+k]
__device__ float g_c;                        // fused bias
__device__ float g_z0[MAXB * MAXS];          // per-row dot with w2[:,k]
__device__ float g_z1[MAXB * MAXS];
__device__ float g_z2[MAXB * MAXS];
__device__ float g_alpha[MAXB * MAXS];
__device__ double g_csum[MAXB * (MAXS / 32)];// per-chunk double alpha sums
__device__ int   g_Ft[MAXB * MAXS];          // fire time indices (compacted)
__device__ float g_Fa1[MAXB * MAXS];         // a1 at fire j
__device__ float g_Fa2[MAXB * MAXS];         // a2 at fire j
__device__ int   g_n[MAXB];

// ---------------------------------------------------------------------------
// Kernel 1a: partial fuse. grid = (9 p-blocks, NCHUNK o-chunks), 256 thr.
// ---------------------------------------------------------------------------
__global__ void k_fuse_part(const float* __restrict__ conv_w,
                            const float* __restrict__ lin_w, int D) {
    const int p = blockIdx.x * 256 + threadIdx.x;     // p = i*3+k
    const int P = D * 3;
    if (p >= P) return;
    const int ch = blockIdx.y;
    const int csz = D / NCHUNK;
    const int o0 = ch * csz;
    float acc = 0.f;
    #pragma unroll 4
    for (int o = o0; o < o0 + csz; o++)
        acc += lin_w[o] * conv_w[(size_t)o * P + p];
    g_part[ch * P + p] = acc;
}

// ---------------------------------------------------------------------------
// Kernel 1b: combine partials (fixed order) + c scalar.
// ---------------------------------------------------------------------------
__global__ void k_fuse_comb(const float* __restrict__ conv_b,
                            const float* __restrict__ lin_w,
                            const float* __restrict__ lin_b, int D) {
    const int P = D * 3;
    if ((int)blockIdx.x == (int)gridDim.x - 1) {
        __shared__ float red[256];
        float s = 0.f;
        for (int o = threadIdx.x; o < D; o += 256) s += lin_w[o] * conv_b[o];
        red[threadIdx.x] = s;
        __syncthreads();
        for (int st = 128; st > 0; st >>= 1) {
            if ((int)threadIdx.x < st) red[threadIdx.x] += red[threadIdx.x + st];
            __syncthreads();
        }
        if (threadIdx.x == 0) g_c = red[0] + lin_b[0];
    } else {
        int p = blockIdx.x * 256 + threadIdx.x;
        if (p < P) {
            float acc = 0.f;
            #pragma unroll
            for (int ch = 0; ch < NCHUNK; ch++) acc += g_part[ch * P + p];
            g_w2[p] = acc;
        }
    }
}

// ---------------------------------------------------------------------------
// Kernel 2: z_k[r] = dot(x[r], w2[:,k]). Warp per row, 8 warps/blk. (R12)
// ---------------------------------------------------------------------------
__global__ void k_z(const float* __restrict__ x, int S, int D) {
    __shared__ __align__(16) float sw2[3 * MAXD];
    for (int idx = threadIdx.x; idx < D * 3; idx += blockDim.x) {
        int i = idx / 3, k = idx - i * 3;
        sw2[k * D + i] = g_w2[idx];
    }
    __syncthreads();

    const int b = blockIdx.y;
    const int warp = threadIdx.x >> 5, lane = threadIdx.x & 31;
    const int r = blockIdx.x * 8 + warp;
    if (r >= S) return;

    const float4* xr  = (const float4*)(x + ((size_t)b * S + r) * D);
    const float4* w0  = (const float4*)(sw2);
    const float4* w1  = (const float4*)(sw2 + D);
    const float4* w2p = (const float4*)(sw2 + 2 * D);
    float a0 = 0.f, a1 = 0.f, a2 = 0.f;

    if (D == MAXD) {
        float4 xv[6];
        #pragma unroll
        for (int u = 0; u < 6; u++) xv[u] = xr[lane + 32 * u];
        #pragma unroll
        for (int u = 0; u < 6; u++) {
            const int m = lane + 32 * u;
            float4 uu = w0[m];
            a0 += uu.x * xv[u].x + uu.y * xv[u].y + uu.z * xv[u].z + uu.w * xv[u].w;
            float4 vv = w1[m];
            a1 += vv.x * xv[u].x + vv.y * xv[u].y + vv.z * xv[u].z + vv.w * xv[u].w;
            float4 ww = w2p[m];
            a2 += ww.x * xv[u].x + ww.y * xv[u].y + ww.z * xv[u].z + ww.w * xv[u].w;
        }
    } else {
        const int M = D >> 2;
        for (int m = lane; m < M; m += 32) {
            float4 xv = xr[m];
            float4 uu = w0[m];
            a0 += uu.x * xv.x + uu.y * xv.y + uu.z * xv.z + uu.w * xv.w;
            float4 vv = w1[m];
            a1 += vv.x * xv.x + vv.y * xv.y + vv.z * xv.z + vv.w * xv.w;
            float4 ww = w2p[m];
            a2 += ww.x * xv.x + ww.y * xv.y + ww.z * xv.z + ww.w * xv.w;
        }
    }
    #pragma unroll
    for (int o = 16; o > 0; o >>= 1) {
        a0 += __shfl_xor_sync(0xffffffffu, a0, o);
        a1 += __shfl_xor_sync(0xffffffffu, a1, o);
        a2 += __shfl_xor_sync(0xffffffffu, a2, o);
    }
    if (lane == 0) {
        size_t idx = (size_t)b * S + r;
        g_z0[idx] = a0; g_z1[idx] = a1; g_z2[idx] = a2;
    }
}

// ---------------------------------------------------------------------------
// Kernel 3: alpha (wide grid) + per-chunk double sums (validated R16).
// ---------------------------------------------------------------------------
__global__ void k_comb(const int* __restrict__ lens, int B, int S) {
    int idx = blockIdx.x * 256 + threadIdx.x;
    float a = 0.f;
    if (idx < B * S) {
        int b = idx / S, t = idx - b * S;
        if (t < lens[b]) {
            float l = g_c + g_z1[idx];
            if (t > 0)     l += g_z0[idx - 1];
            if (t < S - 1) l += g_z2[idx + 1];
            a = 1.f / (1.f + expf(-l));
        }
        g_alpha[idx] = a;
    }
    double d = (double)a;
    #pragma unroll
    for (int o = 16; o > 0; o >>= 1)
        d += __shfl_xor_sync(0xffffffffu, d, o);
    if ((threadIdx.x & 31) == 0 && idx < B * S)
        g_csum[idx >> 5] = d;
}

// ---------------------------------------------------------------------------
// Short-recurrence chain step (validated R10-R16).
// ---------------------------------------------------------------------------
#define CHAINSTEP(aval)                                \
    {   float a   = (aval);                            \
        float s1  = aacc + a;                          \
        float sm1 = s1 - 1.0f;                         \
        bool fire = (s1 >= 1.0f);                      \
        BODY                                           \
        aacc = fire ? sm1 : s1;                        \
        bit++;                                         \
    }
#define CHAIN8(q)  CHAINSTEP((q).x) CHAINSTEP((q).y) CHAINSTEP((q).z) CHAINSTEP((q).w)
#define CHAIN32    { CHAIN8(v0) } { CHAIN8(v1) } { CHAIN8(v2) } { CHAIN8(v3) } \
                   { CHAIN8(v4) } { CHAIN8(v5) } { CHAIN8(v6) } { CHAIN8(v7) }

// ---------------------------------------------------------------------------
// Kernel 4: CIF scan (validated R14/R16): shfl double prefix over
// precomputed chunk sums + float mask/record replay.
// ---------------------------------------------------------------------------
__global__ void k_scan(int S) {
    __shared__ __align__(16) float sa[MAXS];
    __shared__ double sWT;
    __shared__ float  sChk[MAXS / 32];
    __shared__ unsigned int sMask[MAXS / 32];
    __shared__ int    sNfb[MAXS / 32];
    const int b = blockIdx.x;
    const int base = b * S;
    const int NC = S >> 5;

    {
        const float4* src = (const float4*)(g_alpha + base);
        float4* dst = (float4*)sa;
        for (int m = threadIdx.x; m < (S >> 2); m += blockDim.x)
            dst[m] = src[m];
    }

    double v = 0.0, inc = 0.0;
    if ((int)threadIdx.x < NC) {
        v = g_csum[(base >> 5) + threadIdx.x];
        inc = v;
        const int lane = threadIdx.x & 31;
        #pragma unroll
        for (int off = 1; off < 32; off <<= 1) {
            double nv = __shfl_up_sync(0xffffffffu, inc, off);
            if (lane >= off) inc += nv;
        }
    }
    __syncthreads();
    if (threadIdx.x == 31) sWT = inc;
    __syncthreads();
    if ((int)threadIdx.x < NC) {
        if ((int)threadIdx.x >= 32) inc += sWT;
        double pexc = inc - v;
        sChk[threadIdx.x] = (float)(pexc - floor(pexc));
    }
    __syncthreads();

    if ((int)threadIdx.x < NC) {
        const int cb = threadIdx.x;
        float aacc = sChk[cb];
        const float4* q = (const float4*)(sa + (cb << 5));
        float4 v0 = q[0], v1 = q[1], v2 = q[2], v3 = q[3];
        float4 v4 = q[4], v5 = q[5], v6 = q[6], v7 = q[7];
        unsigned int mask = 0u;
        int bit = 0;
        #define BODY mask |= fire ? (1u << bit) : 0u;
        CHAIN32
        #undef BODY
        sMask[cb] = mask;
    }
    __syncthreads();

    if ((int)threadIdx.x < NC) {
        int cnt = 0;
        for (int j = 0; j < (int)threadIdx.x; j++) cnt += __popc(sMask[j]);
        sNfb[threadIdx.x] = cnt;
        if ((int)threadIdx.x == NC - 1)
            g_n[b] = cnt + __popc(sMask[NC - 1]);
    }
    __syncthreads();

    if ((int)threadIdx.x < NC) {
        const int cb = threadIdx.x;
        if (sMask[cb]) {
            float aacc = sChk[cb];
            int pos = base + sNfb[cb];
            const int t0c = cb << 5;
            const float4* q = (const float4*)(sa + t0c);
            float4 v0 = q[0], v1 = q[1], v2 = q[2], v3 = q[3];
            float4 v4 = q[4], v5 = q[5], v6 = q[6], v7 = q[7];
            int bit = 0;
            #define BODY if (fire) { float ra1 = 1.0f - aacc;      \
                                     float ra2 = a - ra1;          \
                                     g_Ft[pos] = t0c + bit;        \
                                     g_Fa1[pos] = ra1;             \
                                     g_Fa2[pos] = ra2; pos++; }
            CHAIN32
            #undef BODY
        }
    }
}

// ---------------------------------------------------------------------------
// Kernel 5: emit — proven serial-4-row/192-thread shape; ONLY change:
// when all 4 rows are real (j0+3 < n), fetch ALL per-row metadata up front
// with one int4 + two float4 + two guarded scalars (MLP~5) instead of 4
// serial per-row metadata round-trips. Weight-selection logic byte-identical.
// ---------------------------------------------------------------------------
__global__ void k_emit(const float* __restrict__ x, float* __restrict__ out,
                       int B, int S, int D, long long out_size) {
    const int b = blockIdx.y;
    const int tid = threadIdx.x;
    const int n = g_n[b];
    const int base = b * S;
    const int j0 = blockIdx.x * 4;

    if (j0 + 3 < n) {
        // ---- fast path: 4 real rows, batched metadata (aligned: j0 % 4 == 0,
        //      base % 4 == 0) ----
        const int4   t1v = *(const int4*)  (g_Ft  + base + j0);
        const float4 a1v = *(const float4*)(g_Fa1 + base + j0);
        const float4 a2v = *(const float4*)(g_Fa2 + base + j0);  // rows j0..j0+2 feed j0+1..j0+3
        const int   tprev = (j0 == 0) ? 0   : g_Ft [base + j0 - 1];
        const float a2prev= (j0 == 0) ? 0.f : g_Fa2[base + j0 - 1];

        const int   t1a[4] = { t1v.x, t1v.y, t1v.z, t1v.w };
        const int   t0a[4] = { tprev, t1v.x, t1v.y, t1v.z };
        const float wa1a[4] = { a1v.x, a1v.y, a1v.z, a1v.w };
        const float wa2a[4] = { a2prev, a2v.x, a2v.y, a2v.z };

        #pragma unroll
        for (int jj = 0; jj < 4; jj++) {
            const int j = j0 + jj;
            const int t1 = t1a[jj];
            const int t0 = t0a[jj];
            const float wa1 = wa1a[jj];
            const float wa2 = wa2a[jj];
            float4 acc = make_float4(0.f, 0.f, 0.f, 0.f);
            #pragma unroll 4
            for (int t = t0; t <= t1; t++) {
                float wgt = (t == t1) ? wa1
                          : ((j > 0 && t == t0) ? wa2 : g_alpha[base + t]);
                const float4 h = ((const float4*)(x + ((size_t)b * S + t) * D))[tid];
                acc.x += wgt * h.x; acc.y += wgt * h.y;
                acc.z += wgt * h.z; acc.w += wgt * h.w;
            }
            ((float4*)(out + ((size_t)b * S + j) * D))[tid] = acc;
        }
    } else {
        // ---- fallback: original per-row path (partial/zero rows) ----
        #pragma unroll
        for (int jj = 0; jj < 4; jj++) {
            const int j = j0 + jj;
            if (j >= S) break;
            float4* orow = (float4*)(out + ((size_t)b * S + j) * D);
            if (j >= n) {
                orow[tid] = make_float4(0.f, 0.f, 0.f, 0.f);
            } else {
                const int t1 = g_Ft[base + j];
                const int t0 = (j == 0) ? 0 : g_Ft[base + j - 1];
                const float wa1 = g_Fa1[base + j];
                const float wa2 = (j == 0) ? 0.f : g_Fa2[base + j - 1];
                float4 acc = make_float4(0.f, 0.f, 0.f, 0.f);
                #pragma unroll 4
                for (int t = t0; t <= t1; t++) {
                    float wgt = (t == t1) ? wa1
                              : ((j > 0 && t == t0) ? wa2 : g_alpha[base + t]);
                    const float4 h = ((const float4*)(x + ((size_t)b * S + t) * D))[tid];
                    acc.x += wgt * h.x; acc.y += wgt * h.y;
                    acc.z += wgt * h.z; acc.w += wgt * h.w;
                }
                orow[tid] = acc;
            }
        }
    }
    if (blockIdx.x == 0 && tid == 0 && out_size >= (long long)B * S * D + B)
        out[(size_t)B * S * D + b] = (float)n;
}

// ---------------------------------------------------------------------------
extern "C" void kernel_launch(void* const* d_in, const int* in_sizes, int n_in,
                              void* d_out, int out_size) {
    const float* x      = (const float*)d_in[0];  // (B,S,D)
    const int*   lens   = (const int*)  d_in[1];  // (B,)
    const float* conv_w = (const float*)d_in[2];  // (D,D,3)
    const float* conv_b = (const float*)d_in[3];  // (D,)
    const float* lin_w  = (const float*)d_in[4];  // (1,D)
    const float* lin_b  = (const float*)d_in[5];  // (1,)

    const int B = in_sizes[1];
    const int D = in_sizes[4];
    const int S = in_sizes[0] / (B * D);
    float* out = (float*)d_out;

    {
        dim3 g1((D * 3 + 255) / 256, NCHUNK);
        k_fuse_part<<<g1, 256>>>(conv_w, lin_w, D);
        k_fuse_comb<<<(D * 3 + 255) / 256 + 1, 256>>>(conv_b, lin_w, lin_b, D);
    }
    {
        dim3 grid((S + 7) / 8, B);
        k_z<<<grid, 256>>>(x, S, D);
    }
    k_comb<<<(B * S + 255) / 256, 256>>>(lens, B, S);   // alpha + chunk sums
    k_scan<<<B, 256>>>(S);                               // prefix + replay only
    {
        dim3 grid((S + 3) / 4, B);
        k_emit<<<grid, D / 4>>>(x, out, B, S, D, (long long)out_size);
    }
}